// round 17
// baseline (speedup 1.0000x reference)
#include <cuda_runtime.h>
#include <cuda_fp16.h>
#include <cstdint>

// ---------------------------------------------------------------------------
// GIN encoder. Fully fused per layer, 5 launches:
//   memset -> fill+cvt -> fused0(gather+HMMA MLP+stats+pool)
//   -> fused1(BN0-folded gather+HMMA+stats+pool, +ow0 tail) -> ow1
// Per-layer fused kernel (128 nodes / 128 threads):
//   phase 1: CSR-bucket gather (fp16 src, fp32 acc) -> rows_h smem fp16
//            (layer 1 folds BN0 affine inline)
//   phase 2: 2x [mma.sync m16n8k16 GEMM + bias + tanh] warp-synchronous
//   phase 3: optional h0 writeback; BN stats + segmented pre-BN pool sums
//   out[g] = scale * poolsum_preBN[g] + cnt[g] * shift
// ---------------------------------------------------------------------------

#define MAX_N 100000
#define MAX_G 1024
#define DIM 64
#define BN_EPS 1e-5f
#define SLOTS 64
#define RS 72              // smem row stride in halves (conflict-free)

#define PS_FLOATS (MAX_G * DIM + 2 * DIM)

__device__ __align__(16) unsigned int g_zeroed[2 * PS_FLOATS + MAX_N + MAX_G];
#define DEGP ((int*)g_zeroed + 2 * PS_FLOATS)
#define CNTP (DEGP + MAX_N)

__device__ __align__(16) __half g_xh [MAX_N * DIM];  // fp16 copy of x
__device__ __align__(16) __half g_h0h[MAX_N * DIM];  // layer-0 pre-BN h, fp16
__device__ __align__(16) int g_srcidx[MAX_N * SLOTS];
// 4 weight matrices fp16, layout [n][k] stride RS (B-operand ready)
__device__ __align__(16) __half g_wh[4 * 64 * RS];

// ---------------- helpers --------------------------------------------------
static __device__ __forceinline__ float tanha(float x) {
    float y;
    asm("tanh.approx.f32 %0, %1;" : "=f"(y) : "f"(x));
    return y;
}
static __device__ __forceinline__ float4 h4_to_f4(uint2 v) {
    __half2 a = *reinterpret_cast<__half2*>(&v.x);
    __half2 b = *reinterpret_cast<__half2*>(&v.y);
    float2 fa = __half22float2(a);
    float2 fb = __half22float2(b);
    return make_float4(fa.x, fa.y, fb.x, fb.y);
}
static __device__ __forceinline__ uint2 f4_to_h4(float4 f) {
    __half2 a = __float22half2_rn(make_float2(f.x, f.y));
    __half2 b = __float22half2_rn(make_float2(f.z, f.w));
    uint2 v;
    v.x = *reinterpret_cast<unsigned int*>(&a);
    v.y = *reinterpret_cast<unsigned int*>(&b);
    return v;
}
static __device__ __forceinline__ void mma16816(
    float* c, const uint32_t* a, const uint32_t* b) {
    asm volatile(
        "mma.sync.aligned.m16n8k16.row.col.f32.f16.f16.f32 "
        "{%0,%1,%2,%3}, {%4,%5,%6,%7}, {%8,%9}, {%0,%1,%2,%3};"
        : "+f"(c[0]), "+f"(c[1]), "+f"(c[2]), "+f"(c[3])
        : "r"(a[0]), "r"(a[1]), "r"(a[2]), "r"(a[3]), "r"(b[0]), "r"(b[1]));
}

// ---------------- bucket fill + graph counts + fp16/weight prep ------------
__global__ void fill_cvt_kernel(const int* __restrict__ ei,
                                const int* __restrict__ batch,
                                const float* __restrict__ x,
                                const float* __restrict__ W1_0,
                                const float* __restrict__ W2_0,
                                const float* __restrict__ W1_1,
                                const float* __restrict__ W2_1,
                                int E, int N, int CV) {
    int t = blockIdx.x * blockDim.x + threadIdx.x;
    if (t < E) {
        int s = __ldg(ei + t);
        int d = __ldg(ei + E + t);
        int pos = atomicAdd(&DEGP[d], 1);
        if (pos < SLOTS) g_srcidx[d * SLOTS + pos] = s;
    }
    if (t < N) atomicAdd(&CNTP[__ldg(batch + t)], 1);
    if (t < CV) {
        float4 v = __ldg(&reinterpret_cast<const float4*>(x)[t]);
        reinterpret_cast<uint2*>(g_xh)[t] = f4_to_h4(v);
    }
    if (t < 4 * 4096) {
        int m = t >> 12, e = t & 4095;
        int k = e >> 6, j = e & 63;   // W[k][j] -> B[n=j][k]
        const float* W = (m == 0) ? W1_0 : (m == 1) ? W2_0
                       : (m == 2) ? W1_1 : W2_1;
        g_wh[m * 64 * RS + j * RS + k] = __float2half(__ldg(W + k * 64 + j));
    }
}

// ---------------- fused layer: gather + HMMA MLP + stats + pool ------------
// 128 nodes / 128 threads. Gather: 16 lanes per node (uint2 chunks), 8 nodes
// concurrent, 16 passes -> rows_h. MLP: warp w owns rows [32w,32w+32),
// 2 m-tiles x 8 n-tiles x 4 k-steps per stage, warp-synchronous.
template <bool AFFINE, bool WRITE_H>
__global__ __launch_bounds__(128) void fused_kernel(
    const __half* __restrict__ xh,
    const __half* __restrict__ W1h, const float* __restrict__ b1,
    const __half* __restrict__ W2h, const float* __restrict__ b2,
    const int* __restrict__ batch, __half* __restrict__ hout,
    float* __restrict__ ps, const float* __restrict__ psPrev,
    const float* __restrict__ gammaPrev, const float* __restrict__ betaPrev,
    float* __restrict__ out, float invN, int N, int G, int mainBlocks) {
    if (AFFINE && (int)blockIdx.x >= mainBlocks) {
        // outwrite duty for the PREVIOUS layer (col_off = 0)
        int idx = ((int)blockIdx.x - mainBlocks) * 128 + threadIdx.x;
        if (idx < G * DIM) {
            int g = idx >> 6, j = idx & 63;
            float mean = __ldg(psPrev + MAX_G * DIM + DIM + j) * invN;
            float var  = __ldg(psPrev + MAX_G * DIM + j) * invN - mean * mean;
            float sc   = __ldg(gammaPrev + j) * rsqrtf(var + BN_EPS);
            float sh   = __ldg(betaPrev + j) - mean * sc;
            out[g * 128 + j] =
                sc * psPrev[idx] + (float)__ldg(&CNTP[g]) * sh;
        }
        return;
    }

    __shared__ __half rows_h[128 * RS];
    __shared__ __half W1s[64 * RS];
    __shared__ __half W2s[64 * RS];
    __shared__ float bias1[64], bias2[64];
    __shared__ int bats[128];

    float* pool   = ps;
    float* stats  = ps + MAX_G * DIM;
    float* totsum = ps + MAX_G * DIM + DIM;

    int tid  = threadIdx.x;
    int wid  = tid >> 5;
    int lane = tid & 31;
    int base = blockIdx.x * 128;
    bool active = (base + tid) < N;

    // weights + bias + batch ids (issue before gather; no barrier needed yet)
    {
        const uint4* s1 = reinterpret_cast<const uint4*>(W1h);
        const uint4* s2 = reinterpret_cast<const uint4*>(W2h);
        uint4* d1 = reinterpret_cast<uint4*>(W1s);
        uint4* d2 = reinterpret_cast<uint4*>(W2s);
        for (int i = tid; i < 64 * RS / 8; i += 128) {
            d1[i] = __ldg(s1 + i);
            d2[i] = __ldg(s2 + i);
        }
    }
    if (tid < 64) {
        bias1[tid] = __ldg(b1 + tid);
        bias2[tid] = __ldg(b2 + tid);
    }
    bats[tid] = __ldg(batch + (active ? (base + tid) : N - 1));

    // ---- phase 1: gather into rows_h ----
    {
        int group = tid >> 4;   // 0..7
        int c     = tid & 15;   // uint2 lane within node row
        const uint2* x2 = reinterpret_cast<const uint2*>(xh);
        float4 sc4, sh4;  // AFFINE constants for this lane's 4 columns
        if (AFFINE) {
            const float4* ss4 = reinterpret_cast<const float4*>(psPrev + MAX_G * DIM);
            const float4* ts4 = reinterpret_cast<const float4*>(psPrev + MAX_G * DIM + DIM);
            float4 ssq = __ldg(&ss4[c]);
            float4 tot = __ldg(&ts4[c]);
            float4 gm = __ldg(&reinterpret_cast<const float4*>(gammaPrev)[c]);
            float4 bt = __ldg(&reinterpret_cast<const float4*>(betaPrev)[c]);
            float mx = tot.x * invN, my = tot.y * invN,
                  mz = tot.z * invN, mw = tot.w * invN;
            sc4.x = gm.x * rsqrtf(ssq.x * invN - mx * mx + BN_EPS);
            sc4.y = gm.y * rsqrtf(ssq.y * invN - my * my + BN_EPS);
            sc4.z = gm.z * rsqrtf(ssq.z * invN - mz * mz + BN_EPS);
            sc4.w = gm.w * rsqrtf(ssq.w * invN - mw * mw + BN_EPS);
            sh4.x = bt.x - mx * sc4.x;
            sh4.y = bt.y - my * sc4.y;
            sh4.z = bt.z - mz * sc4.z;
            sh4.w = bt.w - mw * sc4.w;
        }
#pragma unroll 1
        for (int p = 0; p < 16; p++) {
            int nl = p * 8 + group;
            int node = base + nl;
            float4 acc = make_float4(0.f, 0.f, 0.f, 0.f);
            if (node < N) {
                int deg = __ldg(&DEGP[node]);
                const int4* idx4 =
                    reinterpret_cast<const int4*>(g_srcidx + node * SLOTS);
                acc = h4_to_f4(__ldg(&x2[node * 16 + c]));
                int e = 0;
                for (; e + 4 <= deg; e += 4) {
                    int4 s = __ldg(&idx4[e >> 2]);
                    float4 v0 = h4_to_f4(__ldg(&x2[s.x * 16 + c]));
                    float4 v1 = h4_to_f4(__ldg(&x2[s.y * 16 + c]));
                    float4 v2 = h4_to_f4(__ldg(&x2[s.z * 16 + c]));
                    float4 v3 = h4_to_f4(__ldg(&x2[s.w * 16 + c]));
                    acc.x += (v0.x + v1.x) + (v2.x + v3.x);
                    acc.y += (v0.y + v1.y) + (v2.y + v3.y);
                    acc.z += (v0.z + v1.z) + (v2.z + v3.z);
                    acc.w += (v0.w + v1.w) + (v2.w + v3.w);
                }
                for (; e < deg; e++) {
                    int s = __ldg(g_srcidx + node * SLOTS + e);
                    float4 v0 = h4_to_f4(__ldg(&x2[s * 16 + c]));
                    acc.x += v0.x;
                    acc.y += v0.y;
                    acc.z += v0.z;
                    acc.w += v0.w;
                }
                if (AFFINE) {
                    float f = (float)(1 + deg);
                    acc.x = acc.x * sc4.x + f * sh4.x;
                    acc.y = acc.y * sc4.y + f * sh4.y;
                    acc.z = acc.z * sc4.z + f * sh4.z;
                    acc.w = acc.w * sc4.w + f * sh4.w;
                }
            }
            *reinterpret_cast<uint2*>(rows_h + nl * RS + (c << 2)) =
                f4_to_h4(acc);
        }
    }
    __syncthreads();   // rows + weights + bias + bats ready

    // ---- phase 2: two HMMA stages, warp-synchronous ----
    int gid  = lane >> 2;      // 0..7
    int tq   = lane & 3;       // 0..3
    int mrow = wid * 32 + gid;
    const int RW = RS / 2;     // 36 words
    uint32_t* Rw = reinterpret_cast<uint32_t*>(rows_h);

    float acc[2][8][4];

#pragma unroll 1
    for (int stage = 0; stage < 2; stage++) {
        const uint32_t* Bw = reinterpret_cast<const uint32_t*>(
            stage == 0 ? W1s : W2s);
        const float* bs = stage == 0 ? bias1 : bias2;

#pragma unroll
        for (int mt = 0; mt < 2; mt++)
#pragma unroll
            for (int nt = 0; nt < 8; nt++) {
                float b0v = bs[nt * 8 + tq * 2];
                float b1v = bs[nt * 8 + tq * 2 + 1];
                acc[mt][nt][0] = b0v;
                acc[mt][nt][1] = b1v;
                acc[mt][nt][2] = b0v;
                acc[mt][nt][3] = b1v;
            }
#pragma unroll
        for (int ks = 0; ks < 4; ks++) {
            int kw = ks * 8 + tq;
            uint32_t a[2][4];
#pragma unroll
            for (int mt = 0; mt < 2; mt++) {
                int m0 = mrow + mt * 16;
                a[mt][0] = Rw[m0 * RW + kw];
                a[mt][1] = Rw[(m0 + 8) * RW + kw];
                a[mt][2] = Rw[m0 * RW + kw + 4];
                a[mt][3] = Rw[(m0 + 8) * RW + kw + 4];
            }
            uint32_t b[8][2];
#pragma unroll
            for (int nt = 0; nt < 8; nt++) {
                int n = nt * 8 + gid;
                b[nt][0] = Bw[n * RW + kw];
                b[nt][1] = Bw[n * RW + kw + 4];
            }
#pragma unroll
            for (int mt = 0; mt < 2; mt++)
#pragma unroll
                for (int nt = 0; nt < 8; nt++)
                    mma16816(acc[mt][nt], a[mt], b[nt]);
        }
#pragma unroll
        for (int mt = 0; mt < 2; mt++)
#pragma unroll
            for (int nt = 0; nt < 8; nt++) {
                int m = mrow + mt * 16;
                int nw = (nt * 8 + tq * 2) >> 1;
                __half2 h0 = __float22half2_rn(make_float2(
                    tanha(acc[mt][nt][0]), tanha(acc[mt][nt][1])));
                __half2 h1 = __float22half2_rn(make_float2(
                    tanha(acc[mt][nt][2]), tanha(acc[mt][nt][3])));
                Rw[m * RW + nw] = *reinterpret_cast<uint32_t*>(&h0);
                Rw[(m + 8) * RW + nw] = *reinterpret_cast<uint32_t*>(&h1);
            }
        __syncwarp();
    }
    __syncthreads();

    // zero padded rows (MMA gave them tanh(bias) != 0)
    if (!active) {
        uint2* dst = reinterpret_cast<uint2*>(rows_h + tid * RS);
#pragma unroll
        for (int c2 = 0; c2 < 16; c2++) dst[c2] = make_uint2(0u, 0u);
    }
    __syncthreads();

    if (WRITE_H) {
        __half2* ho = reinterpret_cast<__half2*>(hout);
        for (int i = tid; i < 128 * 32; i += 128) {
            int r = i >> 5, w = i & 31;
            if (base + r < N) {
                ho[(base + r) * 32 + w] =
                    *reinterpret_cast<__half2*>(&Rw[r * RW + w]);
            }
        }
    }

    // phase 3: threads 0..63 pool sums + total; 64..127 sum of squares
    if (tid < 64) {
        int j = tid;
        int cur = bats[0];
        float acc2 = 0.0f;
        float tot = 0.0f;
        for (int r = 0; r < 128; r++) {
            int g = bats[r];
            float v = __half2float(rows_h[r * RS + j]);
            if (g != cur) {
                atomicAdd(&pool[cur * DIM + j], acc2);
                acc2 = 0.0f;
                cur = g;
            }
            acc2 += v;
            tot += v;
        }
        atomicAdd(&pool[cur * DIM + j], acc2);
        atomicAdd(&totsum[j], tot);
    } else {
        int j = tid - 64;
        float s = 0.0f;
        for (int r = 0; r < 128; r++) {
            float v = __half2float(rows_h[r * RS + j]);
            s += v * v;
        }
        atomicAdd(&stats[j], s);
    }
}

// ---------------- output write (BN folded, scale/shift inline) -------------
__global__ void outwrite_kernel(const float* __restrict__ ps,
                                const float* __restrict__ gamma,
                                const float* __restrict__ beta,
                                float* __restrict__ out, int col_off,
                                float invN, int G) {
    int idx = blockIdx.x * blockDim.x + threadIdx.x;
    if (idx >= G * DIM) return;
    int g = idx >> 6, j = idx & 63;
    float mean = __ldg(ps + MAX_G * DIM + DIM + j) * invN;
    float var  = __ldg(ps + MAX_G * DIM + j) * invN - mean * mean;
    float sc   = __ldg(gamma + j) * rsqrtf(var + BN_EPS);
    float sh   = __ldg(beta + j) - mean * sc;
    out[g * 128 + col_off + j] = sc * ps[idx] + (float)__ldg(&CNTP[g]) * sh;
}

// ---------------------------------------------------------------------------
extern "C" void kernel_launch(void* const* d_in, const int* in_sizes, int n_in,
                              void* d_out, int out_size) {
    const float* x       = (const float*)d_in[0];
    const float* W1_0    = (const float*)d_in[1];
    const float* b1_0    = (const float*)d_in[2];
    const float* W2_0    = (const float*)d_in[3];
    const float* b2_0    = (const float*)d_in[4];
    const float* gamma_0 = (const float*)d_in[5];
    const float* beta_0  = (const float*)d_in[6];
    const float* W1_1    = (const float*)d_in[7];
    const float* b1_1    = (const float*)d_in[8];
    const float* W2_1    = (const float*)d_in[9];
    const float* b2_1    = (const float*)d_in[10];
    const float* gamma_1 = (const float*)d_in[11];
    const float* beta_1  = (const float*)d_in[12];
    const int*   ei      = (const int*)d_in[13];
    const int*   batch   = (const int*)d_in[14];

    int N = in_sizes[0] / DIM;
    int E = in_sizes[13] / 2;
    int G = out_size / 128;
    float* out = (float*)d_out;

    void *zero_p, *xh_p, *h0_p, *wh_p;
    cudaGetSymbolAddress(&zero_p, g_zeroed);
    cudaGetSymbolAddress(&xh_p, g_xh);
    cudaGetSymbolAddress(&h0_p, g_h0h);
    cudaGetSymbolAddress(&wh_p, g_wh);

    float* ps0 = (float*)zero_p;
    float* ps1 = ps0 + PS_FLOATS;
    const __half* wh = (const __half*)wh_p;

    int CV = N * DIM / 4;
    int work = (E > N) ? E : N;
    if (CV > work) work = CV;
    if (4 * 4096 > work) work = 4 * 4096;
    int fill_blocks  = (work + 255) / 256;
    int fused_blocks = (N + 127) / 128;
    int ow_tail      = (G * DIM + 127) / 128;
    int ow_blocks    = (G * DIM + 255) / 256;
    float invN = 1.0f / (float)N;

    cudaMemsetAsync(zero_p, 0, sizeof(g_zeroed));
    fill_cvt_kernel<<<fill_blocks, 256>>>(ei, batch, x, W1_0, W2_0, W1_1,
                                          W2_1, E, N, CV);

    // ---------------- layer 0 ----------------
    fused_kernel<false, true><<<fused_blocks, 128>>>(
        (const __half*)xh_p, wh, b1_0, wh + 64 * RS, b2_0, batch,
        (__half*)h0_p, ps0, nullptr, nullptr, nullptr, nullptr,
        invN, N, G, fused_blocks);

    // ---------------- layer 1 (BN0 folded in gather; tail = outwrite0) -----
    fused_kernel<true, false><<<fused_blocks + ow_tail, 128>>>(
        (const __half*)h0_p, wh + 2 * 64 * RS, b1_1, wh + 3 * 64 * RS, b2_1,
        batch, nullptr, ps1, ps0, gamma_0, beta_0, out,
        invN, N, G, fused_blocks);
    outwrite_kernel<<<ow_blocks, 256>>>(ps1, gamma_1, beta_1, out, 64, invN, G);
}